// round 1
// baseline (speedup 1.0000x reference)
#include <cuda_runtime.h>
#include <cstdint>

// Problem constants
#define Bn 8
#define Cn 512
#define Hn 64
#define Wn 64
#define HWn 4096          // 64*64
#define PADW 66           // padded width/height
#define PADSZ (PADW*PADW) // 4356
#define Kdim 4608         // Cn*9

// Scratch: reflect-padded mid activations [B, C, 66, 66]
__device__ float g_midpad[(size_t)Bn * Cn * PADSZ];

// ---------------------------------------------------------------------------
// Kernel 1: instance norm + depthwise 3x3 (reflect) + pointwise + bias,
// fused into a single 3x3 conv on raw x, written directly into the reflect-
// padded scratch layout (border values recomputed via reflect mapping).
// One block per (b,c). 256 threads.
// ---------------------------------------------------------------------------
__global__ void __launch_bounds__(256) k_prep(
    const float* __restrict__ x,
    const float* __restrict__ ws,     // [B*C, 9]
    const float* __restrict__ wp,     // [B*C]
    const float* __restrict__ bias)   // [B*C]
{
    const int bc = blockIdx.x;                 // 0 .. B*C-1
    const float* xp = x + (size_t)bc * HWn;

    __shared__ float xs[HWn];
    __shared__ float red[32];

    const int tid = threadIdx.x;

    float s = 0.f, s2 = 0.f;
    #pragma unroll 4
    for (int i = tid; i < HWn; i += 256) {
        float v = xp[i];
        xs[i] = v;
        s += v;
        s2 += v * v;
    }
    // warp reduce
    #pragma unroll
    for (int o = 16; o; o >>= 1) {
        s  += __shfl_xor_sync(0xffffffffu, s,  o);
        s2 += __shfl_xor_sync(0xffffffffu, s2, o);
    }
    if ((tid & 31) == 0) { red[tid >> 5] = s; red[8 + (tid >> 5)] = s2; }
    __syncthreads();
    if (tid < 32) {
        float a = (tid < 8) ? red[tid] : 0.f;
        float b = (tid < 8) ? red[8 + tid] : 0.f;
        #pragma unroll
        for (int o = 4; o; o >>= 1) {
            a += __shfl_xor_sync(0xffffffffu, a, o);
            b += __shfl_xor_sync(0xffffffffu, b, o);
        }
        if (tid == 0) { red[16] = a; red[17] = b; }
    }
    __syncthreads();

    const float mean = red[16] * (1.f / HWn);
    const float var  = red[17] * (1.f / HWn) - mean * mean;   // biased var
    const float inv  = rsqrtf(var + 1e-5f);
    const float wpv  = wp[bc];
    const float bv   = bias[bc];

    float w[9]; float wsum = 0.f;
    #pragma unroll
    for (int t = 0; t < 9; t++) { w[t] = ws[bc * 9 + t]; wsum += w[t]; }
    const float scale = wpv * inv;
    #pragma unroll
    for (int t = 0; t < 9; t++) w[t] *= scale;
    const float c0 = bv - scale * mean * wsum;

    float* mp = g_midpad + (size_t)bc * PADSZ;

    // Write all 66x66 padded positions. Border positions map to reflected
    // interior coords (pad=1 reflect: -1 -> 1, 64 -> 62).
    for (int i = tid; i < PADSZ; i += 256) {
        const int pi = i / PADW;
        const int pj = i - pi * PADW;
        int h = pi - 1; if (h < 0) h = -h; if (h > 63) h = 126 - h;
        int wcol = pj - 1; if (wcol < 0) wcol = -wcol; if (wcol > 63) wcol = 126 - wcol;

        float acc = c0;
        #pragma unroll
        for (int dy = 0; dy < 3; dy++) {
            int hh = h + dy - 1; if (hh < 0) hh = -hh; if (hh > 63) hh = 126 - hh;
            #pragma unroll
            for (int dx = 0; dx < 3; dx++) {
                int ww = wcol + dx - 1; if (ww < 0) ww = -ww; if (ww > 63) ww = 126 - ww;
                acc += w[dy * 3 + dx] * xs[hh * Wn + ww];
            }
        }
        mp[i] = acc;
    }
}

// ---------------------------------------------------------------------------
// Kernel 2: shared 3x3 conv (C=512 -> C=512) as implicit SGEMM.
//   M = 512 (co), N = 4096 per batch (pixels), K = 4608 (ci*9 + tap)
//   A[m][k] = conv_w flattened (contiguous in k)
//   B[k][p] = g_midpad[b][ci][py+ky][px+kx]
// 128x128 block tile, BK=8, 256 threads, 8x8 microtile (strided frags),
// double-buffered smem.
// ---------------------------------------------------------------------------
__global__ void __launch_bounds__(256, 2) k_conv(
    const float* __restrict__ cw,    // [512, 4608]
    const float* __restrict__ cb,    // [512]
    float* __restrict__ out)         // [B, 512, 64, 64]
{
    const int b      = blockIdx.z;
    const int tile_n = blockIdx.x * 128;   // pixel tile (2 full image rows)
    const int tile_m = blockIdx.y * 128;   // co tile

    __shared__ float As[2][8][128];
    __shared__ float Bs[2][8][128];

    const int tid = threadIdx.x;

    // A tile loaders: thread -> (m = tid/2, k-group = (tid&1)*4), float4 along k
    const int a_m = tid >> 1;
    const int a_k = (tid & 1) * 4;
    const float* aptr = cw + (size_t)(tile_m + a_m) * Kdim + a_k;

    // B tile loaders: thread -> (row r = tid/32, cols c..c+3 = (tid&31)*4)
    const int b_r = tid >> 5;
    const int b_c = (tid & 31) * 4;
    const float* bbase = g_midpad + (size_t)b * Cn * PADSZ;
    const int p0 = tile_n + b_c;          // 4 consecutive pixels, same image row
    const int py = p0 >> 6;
    const int px = p0 & 63;
    const int baseoff = py * PADW + px;

    const int tx = tid & 15;
    const int ty = tid >> 4;

    float acc[8][8];
    #pragma unroll
    for (int i = 0; i < 8; i++)
        #pragma unroll
        for (int j = 0; j < 8; j++) acc[i][j] = 0.f;

    // ---- preload tile 0 into buffer 0 ----
    {
        float4 av = *(const float4*)aptr;
        As[0][a_k + 0][a_m] = av.x;
        As[0][a_k + 1][a_m] = av.y;
        As[0][a_k + 2][a_m] = av.z;
        As[0][a_k + 3][a_m] = av.w;

        const int k = b_r;                 // k0 = 0
        const int ci = k / 9;
        const int t  = k - ci * 9;
        const int ky = t / 3;
        const int kx = t - ky * 3;
        const float* bp = bbase + ci * PADSZ + ky * PADW + kx + baseoff;
        *(float4*)&Bs[0][b_r][b_c] = make_float4(bp[0], bp[1], bp[2], bp[3]);
    }
    __syncthreads();

    const int nk = Kdim / 8;   // 576
    for (int kt = 0; kt < nk; kt++) {
        const int buf = kt & 1;

        float4 a_next;
        float  b_next[4];
        const bool more = (kt + 1 < nk);
        if (more) {
            a_next = *(const float4*)(aptr + (size_t)(kt + 1) * 8);
            const int k = (kt + 1) * 8 + b_r;
            const int ci = k / 9;
            const int t  = k - ci * 9;
            const int ky = t / 3;
            const int kx = t - ky * 3;
            const float* bp = bbase + ci * PADSZ + ky * PADW + kx + baseoff;
            b_next[0] = bp[0]; b_next[1] = bp[1]; b_next[2] = bp[2]; b_next[3] = bp[3];
        }

        // compute on current buffer
        #pragma unroll
        for (int kk = 0; kk < 8; kk++) {
            float ar[8], br[8];
            float4 a0 = *(const float4*)&As[buf][kk][ty * 4];
            float4 a1 = *(const float4*)&As[buf][kk][64 + ty * 4];
            float4 b0 = *(const float4*)&Bs[buf][kk][tx * 4];
            float4 b1 = *(const float4*)&Bs[buf][kk][64 + tx * 4];
            ar[0] = a0.x; ar[1] = a0.y; ar[2] = a0.z; ar[3] = a0.w;
            ar[4] = a1.x; ar[5] = a1.y; ar[6] = a1.z; ar[7] = a1.w;
            br[0] = b0.x; br[1] = b0.y; br[2] = b0.z; br[3] = b0.w;
            br[4] = b1.x; br[5] = b1.y; br[6] = b1.z; br[7] = b1.w;
            #pragma unroll
            for (int i = 0; i < 8; i++)
                #pragma unroll
                for (int j = 0; j < 8; j++)
                    acc[i][j] = fmaf(ar[i], br[j], acc[i][j]);
        }

        if (more) {
            const int nb = buf ^ 1;
            As[nb][a_k + 0][a_m] = a_next.x;
            As[nb][a_k + 1][a_m] = a_next.y;
            As[nb][a_k + 2][a_m] = a_next.z;
            As[nb][a_k + 3][a_m] = a_next.w;
            *(float4*)&Bs[nb][b_r][b_c] = make_float4(b_next[0], b_next[1], b_next[2], b_next[3]);
        }
        __syncthreads();
    }

    // ---- epilogue: add conv_b, write out ----
    float* obase = out + (size_t)b * Cn * HWn + tile_n;
    #pragma unroll
    for (int i = 0; i < 8; i++) {
        const int m = (i < 4) ? (ty * 4 + i) : (64 + ty * 4 + (i - 4));
        const int co = tile_m + m;
        const float bv = cb[co];
        float* orow = obase + (size_t)co * HWn;
        float4 v0 = make_float4(acc[i][0] + bv, acc[i][1] + bv, acc[i][2] + bv, acc[i][3] + bv);
        float4 v1 = make_float4(acc[i][4] + bv, acc[i][5] + bv, acc[i][6] + bv, acc[i][7] + bv);
        *(float4*)&orow[tx * 4]      = v0;
        *(float4*)&orow[64 + tx * 4] = v1;
    }
}

// ---------------------------------------------------------------------------
extern "C" void kernel_launch(void* const* d_in, const int* in_sizes, int n_in,
                              void* d_out, int out_size)
{
    const float* x   = (const float*)d_in[0];   // [8,512,64,64]
    const float* ws  = (const float*)d_in[1];   // [8,512,1,3,3]
    const float* wp  = (const float*)d_in[2];   // [8,512,1,1,1]
    const float* bia = (const float*)d_in[3];   // [8,512]
    const float* cw  = (const float*)d_in[4];   // [512,512,3,3]
    const float* cb  = (const float*)d_in[5];   // [512]
    float* out = (float*)d_out;

    k_prep<<<Bn * Cn, 256>>>(x, ws, wp, bia);

    dim3 grid(HWn / 128, Cn / 128, Bn);        // (32, 4, 8)
    k_conv<<<grid, 256>>>(cw, cb, out);
}

// round 4
// speedup vs baseline: 5.9018x; 5.9018x over previous
#include <cuda_runtime.h>
#include <cuda_fp16.h>
#include <cstdint>

#define Bn 8
#define Cn 512
#define HWn 4096
#define Kdim 4608          // Cn*9

// Scratch: tap-expanded fp16 activations [B, K=C*9, 64*64]  (288 MB)
__device__ __half g_midtap[(size_t)Bn * Kdim * HWn];
// fp16 weights [512, 4608]
__device__ __half g_wA[(size_t)Cn * Kdim];

// ---------------------------------------------------------------------------
__device__ __forceinline__ int refl(int v) {
    if (v < 0) v = -v;
    return v > 63 ? 126 - v : v;
}

// Kernel 0: conv_w fp32 -> fp16
__global__ void k_wcvt(const float* __restrict__ cw) {
    int i = blockIdx.x * 256 + threadIdx.x;
    if (i < Cn * Kdim) g_wA[i] = __float2half(cw[i]);
}

// ---------------------------------------------------------------------------
// Kernel 1: instance norm + depthwise 3x3 (reflect) + pointwise + bias fused
// into one 3x3 conv on raw x; output written as 9 reflect-shifted fp16 planes.
// ---------------------------------------------------------------------------
__global__ void __launch_bounds__(256) k_prep(
    const float* __restrict__ x,
    const float* __restrict__ ws,     // [B*C, 9]
    const float* __restrict__ wp,     // [B*C]
    const float* __restrict__ bias)   // [B*C]
{
    const int bc = blockIdx.x;
    const float* xp = x + (size_t)bc * HWn;

    __shared__ float xs[HWn];
    __shared__ float ms[HWn];
    __shared__ float red[2];
    __shared__ float pr[16];

    const int tid = threadIdx.x;

    float s = 0.f, s2 = 0.f;
    #pragma unroll 4
    for (int i = tid; i < HWn; i += 256) {
        float v = xp[i];
        xs[i] = v;
        s += v; s2 += v * v;
    }
    #pragma unroll
    for (int o = 16; o; o >>= 1) {
        s  += __shfl_xor_sync(0xffffffffu, s,  o);
        s2 += __shfl_xor_sync(0xffffffffu, s2, o);
    }
    if ((tid & 31) == 0) { pr[tid >> 5] = s; pr[8 + (tid >> 5)] = s2; }
    __syncthreads();
    if (tid < 32) {
        float a = (tid < 8) ? pr[tid] : 0.f;
        float b = (tid < 8) ? pr[8 + tid] : 0.f;
        #pragma unroll
        for (int o = 4; o; o >>= 1) {
            a += __shfl_xor_sync(0xffffffffu, a, o);
            b += __shfl_xor_sync(0xffffffffu, b, o);
        }
        if (tid == 0) { red[0] = a; red[1] = b; }
    }
    __syncthreads();

    const float mean = red[0] * (1.f / HWn);
    const float var  = red[1] * (1.f / HWn) - mean * mean;
    const float inv  = rsqrtf(var + 1e-5f);
    const float wpv  = wp[bc];
    const float bv   = bias[bc];

    float w[9]; float wsum = 0.f;
    #pragma unroll
    for (int t = 0; t < 9; t++) { w[t] = ws[bc * 9 + t]; wsum += w[t]; }
    const float scale = wpv * inv;
    #pragma unroll
    for (int t = 0; t < 9; t++) w[t] *= scale;
    const float c0 = bv - scale * mean * wsum;

    for (int i = tid; i < HWn; i += 256) {
        const int y = i >> 6, xx = i & 63;
        float acc = c0;
        #pragma unroll
        for (int dy = 0; dy < 3; dy++) {
            const int yy = refl(y + dy - 1);
            #pragma unroll
            for (int dx = 0; dx < 3; dx++)
                acc += w[dy * 3 + dx] * xs[yy * 64 + refl(xx + dx - 1)];
        }
        ms[i] = acc;
    }
    __syncthreads();

    __half* base = g_midtap + (size_t)bc * 9 * HWn;
    #pragma unroll
    for (int t = 0; t < 9; t++) {
        const int ky = t / 3 - 1, kx = t % 3 - 1;
        __half2* op = (__half2*)(base + (size_t)t * HWn);
        for (int i = tid; i < HWn / 2; i += 256) {
            const int p = i * 2;
            const int y = p >> 6, xx = p & 63;
            const int yy = refl(y + ky);
            float v0 = ms[yy * 64 + refl(xx + kx)];
            float v1 = ms[yy * 64 + refl(xx + 1 + kx)];
            op[i] = __floats2half2_rn(v0, v1);
        }
    }
}

// ---------------------------------------------------------------------------
// Kernel 2: GEMM via mma.sync.m16n8k16 (fp16 in, fp32 accum)
//   per batch:  C[512, 4096] = A[512, 4608] * B[4608, 4096]
// ---------------------------------------------------------------------------
#define BM 128
#define BN 128
#define BK 32
#define STAGES 4
#define A_STRIDE 40                    // halves per A smem row (padded)
#define B_STRIDE 136                   // halves per B smem row (padded)
#define A_BYTES (BM * A_STRIDE * 2)    // 10240
#define B_BYTES (BK * B_STRIDE * 2)    // 8704
#define STAGE_BYTES (A_BYTES + B_BYTES)
#define SMEM_TOTAL (STAGES * STAGE_BYTES)   // 75776

static __device__ __forceinline__ uint32_t smem_u32(const void* p) {
    uint32_t a;
    asm("{ .reg .u64 t; cvta.to.shared.u64 t, %1; cvt.u32.u64 %0, t; }" : "=r"(a) : "l"(p));
    return a;
}

#define CP_ASYNC(dst, src) \
    asm volatile("cp.async.cg.shared.global [%0], [%1], 16;" :: "r"(dst), "l"(src) : "memory")
#define CP_COMMIT() asm volatile("cp.async.commit_group;" ::: "memory")
#define CP_WAIT2()  asm volatile("cp.async.wait_group 2;" ::: "memory")

__device__ __forceinline__ void ldsm4(uint32_t* r, uint32_t addr) {
    asm volatile("ldmatrix.sync.aligned.m8n8.x4.shared.b16 {%0,%1,%2,%3}, [%4];"
        : "=r"(r[0]), "=r"(r[1]), "=r"(r[2]), "=r"(r[3]) : "r"(addr));
}
__device__ __forceinline__ void ldsm4t(uint32_t* r, uint32_t addr) {
    asm volatile("ldmatrix.sync.aligned.m8n8.x4.trans.shared.b16 {%0,%1,%2,%3}, [%4];"
        : "=r"(r[0]), "=r"(r[1]), "=r"(r[2]), "=r"(r[3]) : "r"(addr));
}
__device__ __forceinline__ void mma16816(float* c, const uint32_t* a, uint32_t b0, uint32_t b1) {
    asm volatile(
        "mma.sync.aligned.m16n8k16.row.col.f32.f16.f16.f32 "
        "{%0,%1,%2,%3}, {%4,%5,%6,%7}, {%8,%9}, {%0,%1,%2,%3};"
        : "+f"(c[0]), "+f"(c[1]), "+f"(c[2]), "+f"(c[3])
        : "r"(a[0]), "r"(a[1]), "r"(a[2]), "r"(a[3]), "r"(b0), "r"(b1));
}

__global__ void __launch_bounds__(256) k_conv(
    const float* __restrict__ cb,
    float* __restrict__ out)
{
    extern __shared__ __align__(128) char smem[];
    const uint32_t sbase = smem_u32(smem);

    const int tid  = threadIdx.x;
    const int lane = tid & 31;
    const int warp = tid >> 5;
    const int wm   = warp & 1;          // 2 warps along M (64 rows each)
    const int wn   = warp >> 1;         // 4 warps along N (32 cols each)

    const int tile_m = blockIdx.x * BM;
    const int tile_n = blockIdx.y * BN;
    const int b      = blockIdx.z;

    const __half* wA = g_wA;
    const __half* mt = g_midtap + (size_t)b * Kdim * HWn;

    // ldmatrix per-lane offsets
    const int lrow = (lane & 7) + 8 * ((lane >> 3) & 1);
    const int lcol = 8 * (lane >> 4);

    float acc[4][4][4];
    #pragma unroll
    for (int mi = 0; mi < 4; mi++)
        #pragma unroll
        for (int ni = 0; ni < 4; ni++)
            #pragma unroll
            for (int j = 0; j < 4; j++) acc[mi][ni][j] = 0.f;

    // ---- stage loader ----
    auto load_stage = [&](int s, int k0) {
        const uint32_t sa = sbase + s * STAGE_BYTES;
        const uint32_t sb = sa + A_BYTES;
        #pragma unroll
        for (int i = 0; i < 2; i++) {
            const int slot = tid + i * 256;       // 0..511
            const int row = slot >> 2;            // 0..127
            const int seg = slot & 3;             // 16B segment along k
            const __half* src = wA + (size_t)(tile_m + row) * Kdim + k0 + seg * 8;
            CP_ASYNC(sa + row * (A_STRIDE * 2) + seg * 16, src);
        }
        #pragma unroll
        for (int i = 0; i < 2; i++) {
            const int slot = tid + i * 256;       // 0..511
            const int row = slot >> 4;            // 0..31 (k)
            const int seg = slot & 15;            // 16B segment along n
            const __half* src = mt + (size_t)(k0 + row) * HWn + tile_n + seg * 8;
            CP_ASYNC(sb + row * (B_STRIDE * 2) + seg * 16, src);
        }
    };

    const int NK = Kdim / BK;                     // 144

    // prologue: fill stages 0..2
    #pragma unroll
    for (int s = 0; s < STAGES - 1; s++) {
        load_stage(s, s * BK);
        CP_COMMIT();
    }

    for (int kt = 0; kt < NK; kt++) {
        CP_WAIT2();
        __syncthreads();

        // issue loads for stage kt+3
        const int kn = kt + STAGES - 1;
        if (kn < NK) load_stage(kn & (STAGES - 1), kn * BK);
        CP_COMMIT();

        // compute on stage kt
        const uint32_t sa = sbase + (kt & (STAGES - 1)) * STAGE_BYTES;
        const uint32_t sb = sa + A_BYTES;

        #pragma unroll
        for (int ks = 0; ks < 2; ks++) {
            const int kl = ks * 16;
            uint32_t afr[4][4];
            #pragma unroll
            for (int mi = 0; mi < 4; mi++) {
                const uint32_t addr = sa + 2 * ((64 * wm + 16 * mi + lrow) * A_STRIDE + kl + lcol);
                ldsm4(afr[mi], addr);
            }
            uint32_t bfr[2][4];
            #pragma unroll
            for (int nj = 0; nj < 2; nj++) {
                const uint32_t addr = sb + 2 * ((kl + lrow) * B_STRIDE + 32 * wn + 16 * nj + lcol);
                ldsm4t(bfr[nj], addr);
            }
            #pragma unroll
            for (int mi = 0; mi < 4; mi++)
                #pragma unroll
                for (int ni = 0; ni < 4; ni++)
                    mma16816(acc[mi][ni], afr[mi],
                             bfr[ni >> 1][(ni & 1) * 2], bfr[ni >> 1][(ni & 1) * 2 + 1]);
        }
        __syncthreads();
    }

    // ---- epilogue: add bias, direct global stores ----
    const int g = lane >> 2;
    const int q = lane & 3;
    float* ob = out + (size_t)b * Cn * HWn;
    #pragma unroll
    for (int mi = 0; mi < 4; mi++) {
        const int row0 = tile_m + 64 * wm + 16 * mi + g;
        const float bv0 = cb[row0];
        const float bv1 = cb[row0 + 8];
        #pragma unroll
        for (int ni = 0; ni < 4; ni++) {
            const int col = tile_n + 32 * wn + 8 * ni + 2 * q;
            float2 v0 = make_float2(acc[mi][ni][0] + bv0, acc[mi][ni][1] + bv0);
            float2 v1 = make_float2(acc[mi][ni][2] + bv1, acc[mi][ni][3] + bv1);
            *(float2*)&ob[(size_t)row0 * HWn + col]       = v0;
            *(float2*)&ob[(size_t)(row0 + 8) * HWn + col] = v1;
        }
    }
}

// ---------------------------------------------------------------------------
extern "C" void kernel_launch(void* const* d_in, const int* in_sizes, int n_in,
                              void* d_out, int out_size)
{
    const float* x   = (const float*)d_in[0];
    const float* ws  = (const float*)d_in[1];
    const float* wp  = (const float*)d_in[2];
    const float* bia = (const float*)d_in[3];
    const float* cw  = (const float*)d_in[4];
    const float* cb  = (const float*)d_in[5];
    float* out = (float*)d_out;

    k_wcvt<<<(Cn * Kdim + 255) / 256, 256>>>(cw);
    k_prep<<<Bn * Cn, 256>>>(x, ws, wp, bia);

    cudaFuncSetAttribute(k_conv, cudaFuncAttributeMaxDynamicSharedMemorySize, SMEM_TOTAL);
    dim3 grid(Cn / BM, HWn / BN, Bn);     // (4, 32, 8) — co tiles fastest for B reuse
    k_conv<<<grid, 256, SMEM_TOTAL>>>(cb, out);
}

// round 5
// speedup vs baseline: 6.0456x; 1.0244x over previous
#include <cuda_runtime.h>
#include <cuda_fp16.h>
#include <cstdint>

#define Bn 8
#define Cn 512
#define HWn 4096
#define Kdim 4608          // Cn*9
#define PLROWS 66          // extended rows: image rows -1..64 (reflected)
#define PLSZ (PLROWS * 64) // 4224 halves per plane

// Scratch: 3 kx-shifted fp16 planes, 66 extended rows each: [B*C][3][66][64]  (~99 MB)
__device__ __half g_mid3[(size_t)Bn * Cn * 3 * PLSZ];
// fp16 weights [512, 4608]
__device__ __half g_wA[(size_t)Cn * Kdim];

// ---------------------------------------------------------------------------
__device__ __forceinline__ int refl(int v) {
    if (v < 0) v = -v;
    return v > 63 ? 126 - v : v;
}

// ---------------------------------------------------------------------------
// Kernel 1: weight fp32->fp16 convert (block-strided slice) + instance norm +
// depthwise 3x3 (reflect) + pointwise + bias fused into one 3x3 conv on raw x;
// output written as 3 kx-shifted fp16 planes with 66 reflected-extended rows.
// ---------------------------------------------------------------------------
__global__ void __launch_bounds__(256) k_prep(
    const float* __restrict__ x,
    const float* __restrict__ ws,     // [B*C, 9]
    const float* __restrict__ wp,     // [B*C]
    const float* __restrict__ bias,   // [B*C]
    const float* __restrict__ cw)     // [512*4608]
{
    const int bc = blockIdx.x;
    const int tid = threadIdx.x;

    // ---- weight conversion slice: 576 floats per block (4096 blocks total) ----
    {
        const float2* wsrc = (const float2*)cw;
        __half2* wdst = (__half2*)g_wA;
        const int p0 = bc * 288;
        #pragma unroll
        for (int i = tid; i < 288; i += 256) {
            float2 v = wsrc[p0 + i];
            wdst[p0 + i] = __floats2half2_rn(v.x, v.y);
        }
    }

    const float* xp = x + (size_t)bc * HWn;

    __shared__ float xs[HWn];
    __shared__ float ms[HWn];
    __shared__ float red[2];
    __shared__ float pr[16];

    float s = 0.f, s2 = 0.f;
    #pragma unroll 4
    for (int i = tid; i < HWn; i += 256) {
        float v = xp[i];
        xs[i] = v;
        s += v; s2 += v * v;
    }
    #pragma unroll
    for (int o = 16; o; o >>= 1) {
        s  += __shfl_xor_sync(0xffffffffu, s,  o);
        s2 += __shfl_xor_sync(0xffffffffu, s2, o);
    }
    if ((tid & 31) == 0) { pr[tid >> 5] = s; pr[8 + (tid >> 5)] = s2; }
    __syncthreads();
    if (tid < 32) {
        float a = (tid < 8) ? pr[tid] : 0.f;
        float b = (tid < 8) ? pr[8 + tid] : 0.f;
        #pragma unroll
        for (int o = 4; o; o >>= 1) {
            a += __shfl_xor_sync(0xffffffffu, a, o);
            b += __shfl_xor_sync(0xffffffffu, b, o);
        }
        if (tid == 0) { red[0] = a; red[1] = b; }
    }
    __syncthreads();

    const float mean = red[0] * (1.f / HWn);
    const float var  = red[1] * (1.f / HWn) - mean * mean;
    const float inv  = rsqrtf(var + 1e-5f);
    const float wpv  = wp[bc];
    const float bv   = bias[bc];

    float w[9]; float wsum = 0.f;
    #pragma unroll
    for (int t = 0; t < 9; t++) { w[t] = ws[bc * 9 + t]; wsum += w[t]; }
    const float scale = wpv * inv;
    #pragma unroll
    for (int t = 0; t < 9; t++) w[t] *= scale;
    const float c0 = bv - scale * mean * wsum;

    for (int i = tid; i < HWn; i += 256) {
        const int y = i >> 6, xx = i & 63;
        float acc = c0;
        #pragma unroll
        for (int dy = 0; dy < 3; dy++) {
            const int yy = refl(y + dy - 1);
            #pragma unroll
            for (int dx = 0; dx < 3; dx++)
                acc += w[dy * 3 + dx] * xs[yy * 64 + refl(xx + dx - 1)];
        }
        ms[i] = acc;
    }
    __syncthreads();

    // ---- write 3 kx-shifted planes, rows 0..65 = image rows -1..64 (reflect) ----
    __half2* base = (__half2*)(g_mid3 + (size_t)bc * 3 * PLSZ);
    #pragma unroll
    for (int kx = 0; kx < 3; kx++) {
        for (int i = tid; i < PLSZ / 2; i += 256) {
            const int row = i >> 5;               // extended row 0..65
            const int xx  = (i << 1) & 63;        // even col
            const int rr  = refl(row - 1);
            float v0 = ms[rr * 64 + refl(xx + kx - 1)];
            float v1 = ms[rr * 64 + refl(xx + kx)];
            base[kx * (PLSZ / 2) + i] = __floats2half2_rn(v0, v1);
        }
    }
}

// ---------------------------------------------------------------------------
// Kernel 2: GEMM via mma.sync.m16n8k16 (fp16 in, fp32 accum)
//   per batch:  C[512, 4096] = A[512, 4608] * B[4608, 4096]
//   B gathered from 3-plane mid: k = ci*9 + ky*3 + kx
// ---------------------------------------------------------------------------
#define BM 128
#define BN 128
#define BK 32
#define STAGES 4
#define A_STRIDE 40                    // halves per A smem row (padded)
#define B_STRIDE 136                   // halves per B smem row (padded)
#define A_BYTES (BM * A_STRIDE * 2)    // 10240
#define B_BYTES (BK * B_STRIDE * 2)    // 8704
#define STAGE_BYTES (A_BYTES + B_BYTES)
#define SMEM_TOTAL (STAGES * STAGE_BYTES)   // 75776

static __device__ __forceinline__ uint32_t smem_u32(const void* p) {
    uint32_t a;
    asm("{ .reg .u64 t; cvta.to.shared.u64 t, %1; cvt.u32.u64 %0, t; }" : "=r"(a) : "l"(p));
    return a;
}

#define CP_ASYNC(dst, src) \
    asm volatile("cp.async.cg.shared.global [%0], [%1], 16;" :: "r"(dst), "l"(src) : "memory")
#define CP_COMMIT() asm volatile("cp.async.commit_group;" ::: "memory")
#define CP_WAIT2()  asm volatile("cp.async.wait_group 2;" ::: "memory")

__device__ __forceinline__ void ldsm4(uint32_t* r, uint32_t addr) {
    asm volatile("ldmatrix.sync.aligned.m8n8.x4.shared.b16 {%0,%1,%2,%3}, [%4];"
        : "=r"(r[0]), "=r"(r[1]), "=r"(r[2]), "=r"(r[3]) : "r"(addr));
}
__device__ __forceinline__ void ldsm4t(uint32_t* r, uint32_t addr) {
    asm volatile("ldmatrix.sync.aligned.m8n8.x4.trans.shared.b16 {%0,%1,%2,%3}, [%4];"
        : "=r"(r[0]), "=r"(r[1]), "=r"(r[2]), "=r"(r[3]) : "r"(addr));
}
__device__ __forceinline__ void mma16816(float* c, const uint32_t* a, uint32_t b0, uint32_t b1) {
    asm volatile(
        "mma.sync.aligned.m16n8k16.row.col.f32.f16.f16.f32 "
        "{%0,%1,%2,%3}, {%4,%5,%6,%7}, {%8,%9}, {%0,%1,%2,%3};"
        : "+f"(c[0]), "+f"(c[1]), "+f"(c[2]), "+f"(c[3])
        : "r"(a[0]), "r"(a[1]), "r"(a[2]), "r"(a[3]), "r"(b0), "r"(b1));
}

__global__ void __launch_bounds__(256) k_conv(
    const float* __restrict__ cb,
    float* __restrict__ out)
{
    extern __shared__ __align__(128) char smem[];
    const uint32_t sbase = smem_u32(smem);

    const int tid  = threadIdx.x;
    const int lane = tid & 31;
    const int warp = tid >> 5;
    const int wm   = warp & 1;          // 2 warps along M (64 rows each)
    const int wn   = warp >> 1;         // 4 warps along N (32 cols each)

    const int tile_m = blockIdx.x * BM;
    const int tile_n = blockIdx.y * BN;
    const int py     = tile_n >> 6;     // first image row of the 128-px tile
    const int b      = blockIdx.z;

    const __half* wA = g_wA;
    const __half* m3 = g_mid3 + (size_t)b * Cn * 3 * PLSZ;

    const int lrow = (lane & 7) + 8 * ((lane >> 3) & 1);
    const int lcol = 8 * (lane >> 4);

    float acc[4][4][4];
    #pragma unroll
    for (int mi = 0; mi < 4; mi++)
        #pragma unroll
        for (int ni = 0; ni < 4; ni++)
            #pragma unroll
            for (int j = 0; j < 4; j++) acc[mi][ni][j] = 0.f;

    auto load_stage = [&](int s, int k0) {
        const uint32_t sa = sbase + s * STAGE_BYTES;
        const uint32_t sb = sa + A_BYTES;
        // A: [128 rows co][32 k] — 512 slots of 16B
        #pragma unroll
        for (int i = 0; i < 2; i++) {
            const int slot = tid + i * 256;
            const int row = slot >> 2;
            const int seg = slot & 3;
            const __half* src = wA + (size_t)(tile_m + row) * Kdim + k0 + seg * 8;
            CP_ASYNC(sa + row * (A_STRIDE * 2) + seg * 16, src);
        }
        // B: [32 k-rows][128 px] — 512 slots of 16B, gathered from 3-plane mid
        #pragma unroll
        for (int i = 0; i < 2; i++) {
            const int slot = tid + i * 256;
            const int row = slot >> 4;           // k-row within chunk
            const int seg = slot & 15;
            const int s8  = seg >> 3;            // image row within tile (0/1)
            const int c8  = (seg & 7) * 8;       // col offset
            const int k  = k0 + row;
            const int ci = k / 9;
            const int t  = k - ci * 9;
            const int ky = t / 3;
            const int kx = t - ky * 3;
            const __half* src = m3 + ((size_t)ci * 3 + kx) * PLSZ
                                   + (py + s8 + ky) * 64 + c8;
            CP_ASYNC(sb + row * (B_STRIDE * 2) + seg * 16, src);
        }
    };

    const int NK = Kdim / BK;                    // 144

    #pragma unroll
    for (int s = 0; s < STAGES - 1; s++) {
        load_stage(s, s * BK);
        CP_COMMIT();
    }

    for (int kt = 0; kt < NK; kt++) {
        CP_WAIT2();
        __syncthreads();

        const int kn = kt + STAGES - 1;
        if (kn < NK) load_stage(kn & (STAGES - 1), kn * BK);
        CP_COMMIT();

        const uint32_t sa = sbase + (kt & (STAGES - 1)) * STAGE_BYTES;
        const uint32_t sb = sa + A_BYTES;

        // batch all fragment loads for both k-halves, then all mmas
        uint32_t afr[2][4][4];
        uint32_t bfr[2][2][4];
        #pragma unroll
        for (int ks = 0; ks < 2; ks++) {
            const int kl = ks * 16;
            #pragma unroll
            for (int mi = 0; mi < 4; mi++)
                ldsm4(afr[ks][mi], sa + 2 * ((64 * wm + 16 * mi + lrow) * A_STRIDE + kl + lcol));
            #pragma unroll
            for (int nj = 0; nj < 2; nj++)
                ldsm4t(bfr[ks][nj], sb + 2 * ((kl + lrow) * B_STRIDE + 32 * wn + 16 * nj + lcol));
        }
        #pragma unroll
        for (int ks = 0; ks < 2; ks++)
            #pragma unroll
            for (int mi = 0; mi < 4; mi++)
                #pragma unroll
                for (int ni = 0; ni < 4; ni++)
                    mma16816(acc[mi][ni], afr[ks][mi],
                             bfr[ks][ni >> 1][(ni & 1) * 2], bfr[ks][ni >> 1][(ni & 1) * 2 + 1]);
    }

    // ---- epilogue: add bias, direct global stores ----
    const int g = lane >> 2;
    const int q = lane & 3;
    float* ob = out + (size_t)b * Cn * HWn;
    #pragma unroll
    for (int mi = 0; mi < 4; mi++) {
        const int row0 = tile_m + 64 * wm + 16 * mi + g;
        const float bv0 = cb[row0];
        const float bv1 = cb[row0 + 8];
        #pragma unroll
        for (int ni = 0; ni < 4; ni++) {
            const int col = tile_n + 32 * wn + 8 * ni + 2 * q;
            float2 v0 = make_float2(acc[mi][ni][0] + bv0, acc[mi][ni][1] + bv0);
            float2 v1 = make_float2(acc[mi][ni][2] + bv1, acc[mi][ni][3] + bv1);
            *(float2*)&ob[(size_t)row0 * HWn + col]       = v0;
            *(float2*)&ob[(size_t)(row0 + 8) * HWn + col] = v1;
        }
    }
}

// ---------------------------------------------------------------------------
extern "C" void kernel_launch(void* const* d_in, const int* in_sizes, int n_in,
                              void* d_out, int out_size)
{
    const float* x   = (const float*)d_in[0];
    const float* ws  = (const float*)d_in[1];
    const float* wp  = (const float*)d_in[2];
    const float* bia = (const float*)d_in[3];
    const float* cw  = (const float*)d_in[4];
    const float* cb  = (const float*)d_in[5];
    float* out = (float*)d_out;

    k_prep<<<Bn * Cn, 256>>>(x, ws, wp, bia, cw);

    cudaFuncSetAttribute(k_conv, cudaFuncAttributeMaxDynamicSharedMemorySize, SMEM_TOTAL);
    dim3 grid(Cn / BM, HWn / BN, Bn);     // (4, 32, 8) — co tiles fastest for B reuse
    k_conv<<<grid, 256, SMEM_TOTAL>>>(cb, out);
}

// round 6
// speedup vs baseline: 7.3555x; 1.2167x over previous
#include <cuda_runtime.h>
#include <cuda_fp16.h>
#include <cstdint>

#define Bn 8
#define Cn 512
#define HWn 4096
#define Kdim 4608          // Cn*9
#define PLROWS 66          // extended rows: image rows -1..64 (reflected)
#define PLSZ (PLROWS * 64) // 4224 halves per plane

// Scratch: 3 kx-shifted fp16 planes, 66 extended rows each: [B*C][3][66][64]
__device__ __half g_mid3[(size_t)Bn * Cn * 3 * PLSZ];
// fp16 weights [512, 4608]
__device__ __half g_wA[(size_t)Cn * Kdim];

// ---------------------------------------------------------------------------
__device__ __forceinline__ int refl(int v) {
    if (v < 0) v = -v;
    return v > 63 ? 126 - v : v;
}

// ---------------------------------------------------------------------------
// Kernel 1: weight fp32->fp16 convert slice + instance norm + depthwise 3x3
// (reflect) + pointwise + bias fused into one 3x3 conv on raw x; output
// written as 3 kx-shifted fp16 planes with 66 reflected-extended rows.
// ---------------------------------------------------------------------------
__global__ void __launch_bounds__(256) k_prep(
    const float* __restrict__ x,
    const float* __restrict__ ws,     // [B*C, 9]
    const float* __restrict__ wp,     // [B*C]
    const float* __restrict__ bias,   // [B*C]
    const float* __restrict__ cw)     // [512*4608]
{
    const int bc = blockIdx.x;
    const int tid = threadIdx.x;

    // ---- weight conversion slice: 576 floats per block ----
    {
        const float2* wsrc = (const float2*)cw;
        __half2* wdst = (__half2*)g_wA;
        const int p0 = bc * 288;
        #pragma unroll
        for (int i = tid; i < 288; i += 256) {
            float2 v = wsrc[p0 + i];
            wdst[p0 + i] = __floats2half2_rn(v.x, v.y);
        }
    }

    const float* xp = x + (size_t)bc * HWn;

    __shared__ float xs[HWn];
    __shared__ float ms[HWn];
    __shared__ float red[2];
    __shared__ float pr[16];

    float s = 0.f, s2 = 0.f;
    #pragma unroll 4
    for (int i = tid; i < HWn; i += 256) {
        float v = xp[i];
        xs[i] = v;
        s += v; s2 += v * v;
    }
    #pragma unroll
    for (int o = 16; o; o >>= 1) {
        s  += __shfl_xor_sync(0xffffffffu, s,  o);
        s2 += __shfl_xor_sync(0xffffffffu, s2, o);
    }
    if ((tid & 31) == 0) { pr[tid >> 5] = s; pr[8 + (tid >> 5)] = s2; }
    __syncthreads();
    if (tid < 32) {
        float a = (tid < 8) ? pr[tid] : 0.f;
        float b = (tid < 8) ? pr[8 + tid] : 0.f;
        #pragma unroll
        for (int o = 4; o; o >>= 1) {
            a += __shfl_xor_sync(0xffffffffu, a, o);
            b += __shfl_xor_sync(0xffffffffu, b, o);
        }
        if (tid == 0) { red[0] = a; red[1] = b; }
    }
    __syncthreads();

    const float mean = red[0] * (1.f / HWn);
    const float var  = red[1] * (1.f / HWn) - mean * mean;
    const float inv  = rsqrtf(var + 1e-5f);
    const float wpv  = wp[bc];
    const float bv   = bias[bc];

    float w[9]; float wsum = 0.f;
    #pragma unroll
    for (int t = 0; t < 9; t++) { w[t] = ws[bc * 9 + t]; wsum += w[t]; }
    const float scale = wpv * inv;
    #pragma unroll
    for (int t = 0; t < 9; t++) w[t] *= scale;
    const float c0 = bv - scale * mean * wsum;

    for (int i = tid; i < HWn; i += 256) {
        const int y = i >> 6, xx = i & 63;
        float acc = c0;
        #pragma unroll
        for (int dy = 0; dy < 3; dy++) {
            const int yy = refl(y + dy - 1);
            #pragma unroll
            for (int dx = 0; dx < 3; dx++)
                acc += w[dy * 3 + dx] * xs[yy * 64 + refl(xx + dx - 1)];
        }
        ms[i] = acc;
    }
    __syncthreads();

    __half2* base = (__half2*)(g_mid3 + (size_t)bc * 3 * PLSZ);
    #pragma unroll
    for (int kx = 0; kx < 3; kx++) {
        for (int i = tid; i < PLSZ / 2; i += 256) {
            const int row = i >> 5;
            const int xx  = (i << 1) & 63;
            const int rr  = refl(row - 1);
            float v0 = ms[rr * 64 + refl(xx + kx - 1)];
            float v1 = ms[rr * 64 + refl(xx + kx)];
            base[kx * (PLSZ / 2) + i] = __floats2half2_rn(v0, v1);
        }
    }
}

// ---------------------------------------------------------------------------
// Kernel 2: GEMM via mma.sync.m16n8k16 (fp16 in, fp32 accum)
//   per batch:  C[512, 4096] = A[512, 4608] * B[4608, 4096]
//   BK=64, XOR-swizzled smem, 3 stages, frag double-buffering.
// ---------------------------------------------------------------------------
#define BM 128
#define BN 128
#define BK 64
#define STAGES 3
#define A_BYTES (BM * BK * 2)          // 16384, 128B rows
#define B_BYTES (BK * BN * 2)          // 16384, 256B rows
#define STAGE_BYTES (A_BYTES + B_BYTES)
#define SMEM_TOTAL (STAGES * STAGE_BYTES)   // 98304

static __device__ __forceinline__ uint32_t smem_u32(const void* p) {
    uint32_t a;
    asm("{ .reg .u64 t; cvta.to.shared.u64 t, %1; cvt.u32.u64 %0, t; }" : "=r"(a) : "l"(p));
    return a;
}

#define CP_ASYNC(dst, src) \
    asm volatile("cp.async.cg.shared.global [%0], [%1], 16;" :: "r"(dst), "l"(src) : "memory")
#define CP_COMMIT() asm volatile("cp.async.commit_group;" ::: "memory")
#define CP_WAIT1()  asm volatile("cp.async.wait_group 1;" ::: "memory")

__device__ __forceinline__ void ldsm4(uint32_t* r, uint32_t addr) {
    asm volatile("ldmatrix.sync.aligned.m8n8.x4.shared.b16 {%0,%1,%2,%3}, [%4];"
        : "=r"(r[0]), "=r"(r[1]), "=r"(r[2]), "=r"(r[3]) : "r"(addr));
}
__device__ __forceinline__ void ldsm4t(uint32_t* r, uint32_t addr) {
    asm volatile("ldmatrix.sync.aligned.m8n8.x4.trans.shared.b16 {%0,%1,%2,%3}, [%4];"
        : "=r"(r[0]), "=r"(r[1]), "=r"(r[2]), "=r"(r[3]) : "r"(addr));
}
__device__ __forceinline__ void mma16816(float* c, const uint32_t* a, uint32_t b0, uint32_t b1) {
    asm volatile(
        "mma.sync.aligned.m16n8k16.row.col.f32.f16.f16.f32 "
        "{%0,%1,%2,%3}, {%4,%5,%6,%7}, {%8,%9}, {%0,%1,%2,%3};"
        : "+f"(c[0]), "+f"(c[1]), "+f"(c[2]), "+f"(c[3])
        : "r"(a[0]), "r"(a[1]), "r"(a[2]), "r"(a[3]), "r"(b0), "r"(b1));
}

__global__ void __launch_bounds__(256, 2) k_conv(
    const float* __restrict__ cb,
    float* __restrict__ out)
{
    extern __shared__ __align__(128) char smem[];
    const uint32_t sbase = smem_u32(smem);

    const int tid  = threadIdx.x;
    const int lane = tid & 31;
    const int warp = tid >> 5;
    const int wm   = warp & 1;          // 2 warps along M (64 rows each)
    const int wn   = warp >> 1;         // 4 warps along N (32 cols each)

    const int tile_m = blockIdx.x * BM;
    const int tile_n = blockIdx.y * BN;
    const int py     = tile_n >> 6;     // first image row of the 128-px tile
    const int b      = blockIdx.z;

    const __half* wA = g_wA;
    const __half* m3 = g_mid3 + (size_t)b * Cn * 3 * PLSZ;

    const int lrow = (lane & 7) + 8 * ((lane >> 3) & 1);   // 0..15
    const int lhi  = lane >> 4;                            // 0/1
    const int lsw  = lrow & 7;                             // swizzle phase

    float acc[4][4][4];
    #pragma unroll
    for (int mi = 0; mi < 4; mi++)
        #pragma unroll
        for (int ni = 0; ni < 4; ni++)
            #pragma unroll
            for (int j = 0; j < 4; j++) acc[mi][ni][j] = 0.f;

    // ---- stage loader: 1024 A slots + 1024 B slots of 16B ----
    auto load_stage = [&](int s, int k0) {
        const uint32_t sa = sbase + s * STAGE_BYTES;
        const uint32_t sb = sa + A_BYTES;
        // A: row 0..127, chunk c 0..7 (8 halves each); swizzle c^(row&7)
        #pragma unroll
        for (int i = 0; i < 4; i++) {
            const int slot = tid + i * 256;
            const int row = slot >> 3;
            const int c   = slot & 7;
            const __half* src = wA + (size_t)(tile_m + row) * Kdim + k0 + c * 8;
            CP_ASYNC(sa + row * 128 + ((c ^ (row & 7)) * 16), src);
        }
        // B: k-row r 0..63, chunk c 0..15; swizzle (c&8)|((c^r)&7)
        #pragma unroll
        for (int i = 0; i < 4; i++) {
            const int slot = tid + i * 256;
            const int r = slot >> 4;
            const int c = slot & 15;
            const int s8 = c >> 3;
            const int c8 = (c & 7) * 8;
            const int k  = k0 + r;
            const int ci = k / 9;
            const int t  = k - ci * 9;
            const int ky = t / 3;
            const int kx = t - ky * 3;
            const __half* src = m3 + ((size_t)ci * 3 + kx) * PLSZ
                                   + (py + s8 + ky) * 64 + c8;
            CP_ASYNC(sb + r * 256 + (((c & 8) | ((c ^ r) & 7)) * 16), src);
        }
    };

    const int NK = Kdim / BK;                    // 72

    load_stage(0, 0); CP_COMMIT();
    load_stage(1, BK); CP_COMMIT();

    uint32_t afr[2][4][4];
    uint32_t bfr[2][2][4];

    int stage = 0;                                // kt % 3
    int wstage = 2;                               // (kt+2) % 3
    for (int kt = 0; kt < NK; kt++) {
        CP_WAIT1();
        __syncthreads();

        const int kn = kt + 2;
        if (kn < NK) load_stage(wstage, kn * BK);
        CP_COMMIT();

        const uint32_t sa = sbase + stage * STAGE_BYTES;
        const uint32_t sb = sa + A_BYTES;

        // fragment loader for k-half ks (0..3) into buffer bf
        auto load_frags = [&](int ks, int bf) {
            const int kl = ks * 16;
            const int ca = (kl >> 3) + lhi;               // A chunk 0..7
            #pragma unroll
            for (int mi = 0; mi < 4; mi++) {
                const int row = 64 * wm + 16 * mi + lrow;
                ldsm4(afr[bf][mi], sa + row * 128 + ((ca ^ lsw) * 16));
            }
            #pragma unroll
            for (int nj = 0; nj < 2; nj++) {
                const int c = 4 * wn + 2 * nj + lhi;      // B chunk 0..15
                const int r = kl + lrow;
                ldsm4t(bfr[bf][nj], sb + r * 256 + (((c & 8) | ((c ^ r) & 7)) * 16));
            }
        };

        load_frags(0, 0);
        #pragma unroll
        for (int ks = 0; ks < 4; ks++) {
            if (ks < 3) load_frags(ks + 1, (ks + 1) & 1);
            const int bf = ks & 1;
            #pragma unroll
            for (int mi = 0; mi < 4; mi++)
                #pragma unroll
                for (int ni = 0; ni < 4; ni++)
                    mma16816(acc[mi][ni], afr[bf][mi],
                             bfr[bf][ni >> 1][(ni & 1) * 2], bfr[bf][ni >> 1][(ni & 1) * 2 + 1]);
        }

        stage = (stage == 2) ? 0 : stage + 1;
        wstage = (wstage == 2) ? 0 : wstage + 1;
    }

    // ---- epilogue: add bias, direct global stores ----
    const int g = lane >> 2;
    const int q = lane & 3;
    float* ob = out + (size_t)b * Cn * HWn;
    #pragma unroll
    for (int mi = 0; mi < 4; mi++) {
        const int row0 = tile_m + 64 * wm + 16 * mi + g;
        const float bv0 = cb[row0];
        const float bv1 = cb[row0 + 8];
        #pragma unroll
        for (int ni = 0; ni < 4; ni++) {
            const int col = tile_n + 32 * wn + 8 * ni + 2 * q;
            float2 v0 = make_float2(acc[mi][ni][0] + bv0, acc[mi][ni][1] + bv0);
            float2 v1 = make_float2(acc[mi][ni][2] + bv1, acc[mi][ni][3] + bv1);
            *(float2*)&ob[(size_t)row0 * HWn + col]       = v0;
            *(float2*)&ob[(size_t)(row0 + 8) * HWn + col] = v1;
        }
    }
}

// ---------------------------------------------------------------------------
extern "C" void kernel_launch(void* const* d_in, const int* in_sizes, int n_in,
                              void* d_out, int out_size)
{
    const float* x   = (const float*)d_in[0];
    const float* ws  = (const float*)d_in[1];
    const float* wp  = (const float*)d_in[2];
    const float* bia = (const float*)d_in[3];
    const float* cw  = (const float*)d_in[4];
    const float* cb  = (const float*)d_in[5];
    float* out = (float*)d_out;

    k_prep<<<Bn * Cn, 256>>>(x, ws, wp, bia, cw);

    cudaFuncSetAttribute(k_conv, cudaFuncAttributeMaxDynamicSharedMemorySize, SMEM_TOTAL);
    dim3 grid(Cn / BM, HWn / BN, Bn);     // (4, 32, 8) — co tiles fastest for B reuse
    k_conv<<<grid, 256, SMEM_TOTAL>>>(cb, out);
}

// round 7
// speedup vs baseline: 8.0565x; 1.0953x over previous
#include <cuda_runtime.h>
#include <cuda_fp16.h>
#include <cstdint>

#define Bn 8
#define Cn 512
#define HWn 4096
#define Kdim 4608          // Cn*9
#define PLROWS 66          // extended rows: image rows -1..64 (reflected)
#define PLSZ (PLROWS * 64) // 4224 halves per plane

// Scratch: 3 kx-shifted fp16 planes, 66 extended rows each: [B*C][3][66][64]
__device__ __half g_mid3[(size_t)Bn * Cn * 3 * PLSZ];
// fp16 weights, tap-major k: [512][t*512 + ci]
__device__ __half g_wA2[(size_t)Cn * Kdim];

// ---------------------------------------------------------------------------
__device__ __forceinline__ int refl(int v) {
    if (v < 0) v = -v;
    return v > 63 ? 126 - v : v;
}

// ---------------------------------------------------------------------------
// Kernel 1: weight fp32->fp16 convert + tap-major permute (block slice) +
// instance norm + depthwise 3x3 (reflect) + pointwise + bias fused into one
// 3x3 conv on raw x; output written as 3 kx-shifted fp16 planes (66 ext rows).
// ---------------------------------------------------------------------------
__global__ void __launch_bounds__(256) k_prep(
    const float* __restrict__ x,
    const float* __restrict__ ws,     // [B*C, 9]
    const float* __restrict__ wp,     // [B*C]
    const float* __restrict__ bias,   // [B*C]
    const float* __restrict__ cw)     // [512*4608] (m, ci*9+t)
{
    const int bc = blockIdx.x;
    const int tid = threadIdx.x;

    // ---- weight convert+permute slice: 576 floats per block ----
    {
        const int p0 = bc * 576;
        for (int i = tid; i < 576; i += 256) {
            const int p = p0 + i;
            const int m   = p / Kdim;
            const int rem = p - m * Kdim;
            const int ci  = rem / 9;
            const int t   = rem - ci * 9;
            g_wA2[(size_t)m * Kdim + t * 512 + ci] = __float2half(cw[p]);
        }
    }

    const float* xp = x + (size_t)bc * HWn;

    __shared__ float xs[HWn];
    __shared__ float ms[HWn];
    __shared__ float red[2];
    __shared__ float pr[16];

    float s = 0.f, s2 = 0.f;
    #pragma unroll 4
    for (int i = tid; i < HWn; i += 256) {
        float v = xp[i];
        xs[i] = v;
        s += v; s2 += v * v;
    }
    #pragma unroll
    for (int o = 16; o; o >>= 1) {
        s  += __shfl_xor_sync(0xffffffffu, s,  o);
        s2 += __shfl_xor_sync(0xffffffffu, s2, o);
    }
    if ((tid & 31) == 0) { pr[tid >> 5] = s; pr[8 + (tid >> 5)] = s2; }
    __syncthreads();
    if (tid < 32) {
        float a = (tid < 8) ? pr[tid] : 0.f;
        float b = (tid < 8) ? pr[8 + tid] : 0.f;
        #pragma unroll
        for (int o = 4; o; o >>= 1) {
            a += __shfl_xor_sync(0xffffffffu, a, o);
            b += __shfl_xor_sync(0xffffffffu, b, o);
        }
        if (tid == 0) { red[0] = a; red[1] = b; }
    }
    __syncthreads();

    const float mean = red[0] * (1.f / HWn);
    const float var  = red[1] * (1.f / HWn) - mean * mean;
    const float inv  = rsqrtf(var + 1e-5f);
    const float wpv  = wp[bc];
    const float bv   = bias[bc];

    float w[9]; float wsum = 0.f;
    #pragma unroll
    for (int t = 0; t < 9; t++) { w[t] = ws[bc * 9 + t]; wsum += w[t]; }
    const float scale = wpv * inv;
    #pragma unroll
    for (int t = 0; t < 9; t++) w[t] *= scale;
    const float c0 = bv - scale * mean * wsum;

    for (int i = tid; i < HWn; i += 256) {
        const int y = i >> 6, xx = i & 63;
        float acc = c0;
        #pragma unroll
        for (int dy = 0; dy < 3; dy++) {
            const int yy = refl(y + dy - 1);
            #pragma unroll
            for (int dx = 0; dx < 3; dx++)
                acc += w[dy * 3 + dx] * xs[yy * 64 + refl(xx + dx - 1)];
        }
        ms[i] = acc;
    }
    __syncthreads();

    __half2* base = (__half2*)(g_mid3 + (size_t)bc * 3 * PLSZ);
    #pragma unroll
    for (int kx = 0; kx < 3; kx++) {
        for (int i = tid; i < PLSZ / 2; i += 256) {
            const int row = i >> 5;
            const int xx  = (i << 1) & 63;
            const int rr  = refl(row - 1);
            float v0 = ms[rr * 64 + refl(xx + kx - 1)];
            float v1 = ms[rr * 64 + refl(xx + kx)];
            base[kx * (PLSZ / 2) + i] = __floats2half2_rn(v0, v1);
        }
    }
}

// ---------------------------------------------------------------------------
// Kernel 2: GEMM via mma.sync.m16n8k16 (fp16 in, fp32 accum)
//   per batch:  C[512, 4096] = A'[512, 4608] * B'[4608, 4096], tap-major k'
//   BK=64, XOR-swizzled smem, 3 stages, frag double-buffering.
// ---------------------------------------------------------------------------
#define BM 128
#define BN 128
#define BK 64
#define STAGES 3
#define A_BYTES (BM * BK * 2)          // 16384, 128B rows
#define B_BYTES (BK * BN * 2)          // 16384, 256B rows
#define STAGE_BYTES (A_BYTES + B_BYTES)
#define SMEM_TOTAL (STAGES * STAGE_BYTES)   // 98304

static __device__ __forceinline__ uint32_t smem_u32(const void* p) {
    uint32_t a;
    asm("{ .reg .u64 t; cvta.to.shared.u64 t, %1; cvt.u32.u64 %0, t; }" : "=r"(a) : "l"(p));
    return a;
}

#define CP_ASYNC(dst, src) \
    asm volatile("cp.async.cg.shared.global [%0], [%1], 16;" :: "r"(dst), "l"(src) : "memory")
#define CP_COMMIT() asm volatile("cp.async.commit_group;" ::: "memory")
#define CP_WAIT1()  asm volatile("cp.async.wait_group 1;" ::: "memory")

__device__ __forceinline__ void ldsm4(uint32_t* r, uint32_t addr) {
    asm volatile("ldmatrix.sync.aligned.m8n8.x4.shared.b16 {%0,%1,%2,%3}, [%4];"
        : "=r"(r[0]), "=r"(r[1]), "=r"(r[2]), "=r"(r[3]) : "r"(addr));
}
__device__ __forceinline__ void ldsm4t(uint32_t* r, uint32_t addr) {
    asm volatile("ldmatrix.sync.aligned.m8n8.x4.trans.shared.b16 {%0,%1,%2,%3}, [%4];"
        : "=r"(r[0]), "=r"(r[1]), "=r"(r[2]), "=r"(r[3]) : "r"(addr));
}
__device__ __forceinline__ void mma16816(float* c, const uint32_t* a, uint32_t b0, uint32_t b1) {
    asm volatile(
        "mma.sync.aligned.m16n8k16.row.col.f32.f16.f16.f32 "
        "{%0,%1,%2,%3}, {%4,%5,%6,%7}, {%8,%9}, {%0,%1,%2,%3};"
        : "+f"(c[0]), "+f"(c[1]), "+f"(c[2]), "+f"(c[3])
        : "r"(a[0]), "r"(a[1]), "r"(a[2]), "r"(a[3]), "r"(b0), "r"(b1));
}

__global__ void __launch_bounds__(256, 2) k_conv(
    const float* __restrict__ cb,
    float* __restrict__ out)
{
    extern __shared__ __align__(128) char smem[];
    const uint32_t sbase = smem_u32(smem);

    const int tid  = threadIdx.x;
    const int lane = tid & 31;
    const int warp = tid >> 5;
    const int wm   = warp & 1;          // 2 warps along M (64 rows each)
    const int wn   = warp >> 1;         // 4 warps along N (32 cols each)

    const int tile_m = blockIdx.x * BM;
    const int tile_n = blockIdx.y * BN;
    const int py     = tile_n >> 6;     // first image row of the 128-px tile
    const int b      = blockIdx.z;

    const __half* wA = g_wA2;
    const __half* m3 = g_mid3 + (size_t)b * Cn * 3 * PLSZ;

    const int lrow = (lane & 7) + 8 * ((lane >> 3) & 1);   // 0..15
    const int lhi  = lane >> 4;                            // 0/1
    const int lsw  = lrow & 7;                             // swizzle phase

    float acc[4][4][4];
    #pragma unroll
    for (int mi = 0; mi < 4; mi++)
        #pragma unroll
        for (int ni = 0; ni < 4; ni++)
            #pragma unroll
            for (int j = 0; j < 4; j++) acc[mi][ni][j] = 0.f;

    // ---- stage loader: chunk kn (64 k'-rows, constant tap) ----
    auto load_stage = [&](int s, int kn) {
        const uint32_t sa = sbase + s * STAGE_BYTES;
        const uint32_t sb = sa + A_BYTES;
        const int k0 = kn * BK;
        // A: row 0..127, chunk c 0..7 (8 halves); swizzle c^(row&7)
        #pragma unroll
        for (int i = 0; i < 4; i++) {
            const int slot = tid + i * 256;
            const int row = slot >> 3;
            const int c   = slot & 7;
            const __half* src = wA + (size_t)(tile_m + row) * Kdim + k0 + c * 8;
            CP_ASYNC(sa + row * 128 + ((c ^ (row & 7)) * 16), src);
        }
        // B: tap-major — tap constant over the chunk, ci affine in slot
        const int t  = kn >> 3;          // tap 0..8
        const int ky = t / 3;
        const int kx = t - 3 * ky;
        const int ci0 = (kn & 7) * 64;
        const __half* tb = m3 + (size_t)kx * PLSZ + (py + ky) * 64;
        #pragma unroll
        for (int i = 0; i < 4; i++) {
            const int slot = tid + i * 256;
            const int r  = slot >> 4;            // k-row within chunk = ci offset
            const int c  = slot & 15;
            const int s8 = c >> 3;               // image row within tile (0/1)
            const int c8 = (c & 7) * 8;
            const __half* src = tb + (size_t)(ci0 + r) * (3 * PLSZ) + s8 * 64 + c8;
            CP_ASYNC(sb + r * 256 + (((c & 8) | ((c ^ r) & 7)) * 16), src);
        }
    };

    const int NK = Kdim / BK;                    // 72

    load_stage(0, 0); CP_COMMIT();
    load_stage(1, 1); CP_COMMIT();

    uint32_t afr[2][4][4];
    uint32_t bfr[2][2][4];

    int stage = 0;
    int wstage = 2;
    for (int kt = 0; kt < NK; kt++) {
        CP_WAIT1();
        __syncthreads();

        const int kn = kt + 2;
        if (kn < NK) load_stage(wstage, kn);
        CP_COMMIT();

        const uint32_t sa = sbase + stage * STAGE_BYTES;
        const uint32_t sb = sa + A_BYTES;

        auto load_frags = [&](int ks, int bf) {
            const int kl = ks * 16;
            const int ca = (kl >> 3) + lhi;               // A chunk 0..7
            #pragma unroll
            for (int mi = 0; mi < 4; mi++) {
                const int row = 64 * wm + 16 * mi + lrow;
                ldsm4(afr[bf][mi], sa + row * 128 + ((ca ^ lsw) * 16));
            }
            #pragma unroll
            for (int nj = 0; nj < 2; nj++) {
                const int c = 4 * wn + 2 * nj + lhi;      // B chunk 0..15
                const int r = kl + lrow;
                ldsm4t(bfr[bf][nj], sb + r * 256 + (((c & 8) | ((c ^ r) & 7)) * 16));
            }
        };

        load_frags(0, 0);
        #pragma unroll
        for (int ks = 0; ks < 4; ks++) {
            if (ks < 3) load_frags(ks + 1, (ks + 1) & 1);
            const int bf = ks & 1;
            #pragma unroll
            for (int mi = 0; mi < 4; mi++)
                #pragma unroll
                for (int ni = 0; ni < 4; ni++)
                    mma16816(acc[mi][ni], afr[bf][mi],
                             bfr[bf][ni >> 1][(ni & 1) * 2], bfr[bf][ni >> 1][(ni & 1) * 2 + 1]);
        }

        stage = (stage == 2) ? 0 : stage + 1;
        wstage = (wstage == 2) ? 0 : wstage + 1;
    }

    // ---- epilogue: add bias, direct global stores ----
    const int g = lane >> 2;
    const int q = lane & 3;
    float* ob = out + (size_t)b * Cn * HWn;
    #pragma unroll
    for (int mi = 0; mi < 4; mi++) {
        const int row0 = tile_m + 64 * wm + 16 * mi + g;
        const float bv0 = cb[row0];
        const float bv1 = cb[row0 + 8];
        #pragma unroll
        for (int ni = 0; ni < 4; ni++) {
            const int col = tile_n + 32 * wn + 8 * ni + 2 * q;
            float2 v0 = make_float2(acc[mi][ni][0] + bv0, acc[mi][ni][1] + bv0);
            float2 v1 = make_float2(acc[mi][ni][2] + bv1, acc[mi][ni][3] + bv1);
            *(float2*)&ob[(size_t)row0 * HWn + col]       = v0;
            *(float2*)&ob[(size_t)(row0 + 8) * HWn + col] = v1;
        }
    }
}

// ---------------------------------------------------------------------------
extern "C" void kernel_launch(void* const* d_in, const int* in_sizes, int n_in,
                              void* d_out, int out_size)
{
    const float* x   = (const float*)d_in[0];
    const float* ws  = (const float*)d_in[1];
    const float* wp  = (const float*)d_in[2];
    const float* bia = (const float*)d_in[3];
    const float* cw  = (const float*)d_in[4];
    const float* cb  = (const float*)d_in[5];
    float* out = (float*)d_out;

    k_prep<<<Bn * Cn, 256>>>(x, ws, wp, bia, cw);

    cudaFuncSetAttribute(k_conv, cudaFuncAttributeMaxDynamicSharedMemorySize, SMEM_TOTAL);
    dim3 grid(Cn / BM, HWn / BN, Bn);     // (4, 32, 8) — co tiles fastest for B reuse
    k_conv<<<grid, 256, SMEM_TOTAL>>>(cb, out);
}